// round 1
// baseline (speedup 1.0000x reference)
#include <cuda_runtime.h>
#include <math.h>

#define TOKENS 4096
#define HD 1024
#define ID 1024
#define NE 8
#define NPAIR (TOKENS * 2)

// ---------------- scratch (device globals; no allocations allowed) ----------
__device__ float g_h_shared[(size_t)TOKENS * ID];   // shared-expert hidden
__device__ float g_o_shared[(size_t)TOKENS * HD];   // shared-expert output
__device__ float g_h_routed[(size_t)NPAIR * ID];    // routed hidden per pair p = t*2+k
__device__ float g_o_routed[(size_t)NPAIR * HD];    // routed down output per pair
__device__ float g_topw[NPAIR];
__device__ int   g_counts[NE];
__device__ int   g_lists[NE * TOKENS];              // pair ids per expert

// ---------------- small helpers --------------------------------------------
typedef unsigned long long ull;

__device__ __forceinline__ ull splat2(float a) {
    ull d; asm("mov.b64 %0, {%1, %1};" : "=l"(d) : "f"(a)); return d;
}
__device__ __forceinline__ void fma2(ull& d, ull a, ull b) {
    asm("fma.rn.f32x2 %0, %1, %2, %0;" : "+l"(d) : "l"(a), "l"(b));
}
__device__ __forceinline__ float2 unpack2(ull v) {
    float2 f; asm("mov.b64 {%0, %1}, %2;" : "=f"(f.x), "=f"(f.y) : "l"(v)); return f;
}

// ---------------- init ------------------------------------------------------
__global__ void zero_counts_k() {
    if (threadIdx.x < NE) g_counts[threadIdx.x] = 0;
}

// ---------------- router: logits -> softmax -> top2 + compaction ------------
__global__ void router_k(const float* __restrict__ x, const float* __restrict__ rw) {
    int warp = (blockIdx.x * blockDim.x + threadIdx.x) >> 5;
    int lane = threadIdx.x & 31;
    if (warp >= TOKENS) return;
    const float* xr = x + (size_t)warp * HD;
    float acc[NE];
#pragma unroll
    for (int e = 0; e < NE; e++) acc[e] = 0.f;
    for (int h = lane; h < HD; h += 32) {
        float xv = xr[h];
#pragma unroll
        for (int e = 0; e < NE; e++) acc[e] = fmaf(xv, rw[e * HD + h], acc[e]);
    }
#pragma unroll
    for (int e = 0; e < NE; e++) {
#pragma unroll
        for (int o = 16; o > 0; o >>= 1)
            acc[e] += __shfl_down_sync(0xffffffffu, acc[e], o);
    }
    if (lane == 0) {
        float mx = acc[0];
#pragma unroll
        for (int e = 1; e < NE; e++) mx = fmaxf(mx, acc[e]);
        float s[NE]; float sum = 0.f;
#pragma unroll
        for (int e = 0; e < NE; e++) { s[e] = expf(acc[e] - mx); sum += s[e]; }
        float inv = 1.f / sum;
        // greedy top-2, ties -> lowest index (matches jax.lax.top_k)
        int i1 = 0; float v1 = s[0];
#pragma unroll
        for (int e = 1; e < NE; e++) if (s[e] > v1) { v1 = s[e]; i1 = e; }
        int i2 = -1; float v2 = -1.f;
#pragma unroll
        for (int e = 0; e < NE; e++) if (e != i1 && s[e] > v2) { v2 = s[e]; i2 = e; }
        int t = warp;
        g_topw[t * 2 + 0] = v1 * inv;   // routed_scaling_factor = 1.0
        g_topw[t * 2 + 1] = v2 * inv;
        int s1 = atomicAdd(&g_counts[i1], 1); g_lists[i1 * TOKENS + s1] = t * 2;
        int s2 = atomicAdd(&g_counts[i2], 1); g_lists[i2 * TOKENS + s2] = t * 2 + 1;
    }
}

// ---------------- tiled GEMM (optionally dual-B fused SwiGLU, optionally gathered)
// GMODE: 0 = plain rows, 1 = gather (src = pair>>1 into x, dst = pair),
//        2 = gather (src = pair, dst = pair)
#define BM 128
#define BN 64
#define BK 16

template<bool DUAL, int GMODE>
__global__ __launch_bounds__(256)
void gemm_k(const float* __restrict__ A, const float* __restrict__ B0in,
            const float* __restrict__ B1in, float* __restrict__ C,
            int N, int Kd, long bstride)
{
    __shared__ __align__(16) float As[BK * BM];
    __shared__ __align__(16) float Bs0[BK * BN];
    __shared__ __align__(16) float Bs1[DUAL ? BK * BN : 1];
    __shared__ int s_src[GMODE ? BM : 1];
    __shared__ int s_dst[GMODE ? BM : 1];

    const int tid = threadIdx.x;
    int mtile = blockIdx.y;
    const float* B0 = B0in;
    const float* B1 = B1in;

    if (GMODE) {
        const int MT = TOKENS / BM;
        int e = blockIdx.y / MT;
        mtile = blockIdx.y % MT;
        int count = g_counts[e];
        if (mtile * BM >= count) return;
        B0 = B0in + (size_t)e * bstride;
        if (DUAL) B1 = B1in + (size_t)e * bstride;
        for (int r = tid; r < BM; r += 256) {
            int idx = mtile * BM + r;
            if (idx < count) {
                int p = g_lists[e * TOKENS + idx];
                s_dst[r] = p;
                s_src[r] = (GMODE == 1) ? (p >> 1) : p;
            } else { s_dst[r] = -1; s_src[r] = 0; }
        }
        __syncthreads();
    }

    const int tx = tid & 15;   // 16 cols of 4 -> BN=64
    const int ty = tid >> 4;   // 16 rows of 8 -> BM=128
    const int bn0 = blockIdx.x * BN;

    ull acc0[8][2];
    ull acc1[8][2];
#pragma unroll
    for (int i = 0; i < 8; i++) {
        acc0[i][0] = 0ull; acc0[i][1] = 0ull;
        if (DUAL) { acc1[i][0] = 0ull; acc1[i][1] = 0ull; }
    }

    for (int k0 = 0; k0 < Kd; k0 += BK) {
        // A tile -> transposed As[k][m]
#pragma unroll
        for (int it = 0; it < 2; it++) {
            int chunk = tid + it * 256;
            int row = chunk >> 2;
            int kq = (chunk & 3) << 2;
            int src = GMODE ? s_src[row] : (mtile * BM + row);
            float4 av = *(const float4*)(A + (size_t)src * Kd + k0 + kq);
            As[(kq + 0) * BM + row] = av.x;
            As[(kq + 1) * BM + row] = av.y;
            As[(kq + 2) * BM + row] = av.z;
            As[(kq + 3) * BM + row] = av.w;
        }
        // B tile(s), row-major [BK][BN]
        {
            int brow = tid >> 4;
            int bcol = (tid & 15) << 2;
            *(float4*)(Bs0 + brow * BN + bcol) =
                *(const float4*)(B0 + (size_t)(k0 + brow) * N + bn0 + bcol);
            if (DUAL)
                *(float4*)(Bs1 + brow * BN + bcol) =
                    *(const float4*)(B1 + (size_t)(k0 + brow) * N + bn0 + bcol);
        }
        __syncthreads();
#pragma unroll
        for (int kk = 0; kk < BK; kk++) {
            float4 av0 = *(const float4*)(As + kk * BM + ty * 8);
            float4 av1 = *(const float4*)(As + kk * BM + ty * 8 + 4);
            float a[8] = {av0.x, av0.y, av0.z, av0.w, av1.x, av1.y, av1.z, av1.w};
            ulonglong2 b0 = *(const ulonglong2*)(Bs0 + kk * BN + tx * 4);
            ulonglong2 b1;
            if (DUAL) b1 = *(const ulonglong2*)(Bs1 + kk * BN + tx * 4);
#pragma unroll
            for (int i = 0; i < 8; i++) {
                ull a2 = splat2(a[i]);
                fma2(acc0[i][0], a2, b0.x);
                fma2(acc0[i][1], a2, b0.y);
                if (DUAL) {
                    fma2(acc1[i][0], a2, b1.x);
                    fma2(acc1[i][1], a2, b1.y);
                }
            }
        }
        __syncthreads();
    }

    // epilogue
#pragma unroll
    for (int i = 0; i < 8; i++) {
        int r = ty * 8 + i;
        int dst = GMODE ? s_dst[r] : (mtile * BM + r);
        if (GMODE && dst < 0) continue;
        float2 c0 = unpack2(acc0[i][0]);
        float2 c1 = unpack2(acc0[i][1]);
        float4 v;
        if (DUAL) {
            float2 u0 = unpack2(acc1[i][0]);
            float2 u1 = unpack2(acc1[i][1]);
            v.x = u0.x / (1.f + expf(-c0.x));
            v.y = u0.y / (1.f + expf(-c0.y));
            v.z = u1.x / (1.f + expf(-c1.x));
            v.w = u1.y / (1.f + expf(-c1.y));
        } else {
            v.x = c0.x; v.y = c0.y; v.z = c1.x; v.w = c1.y;
        }
        *(float4*)(C + (size_t)dst * N + bn0 + tx * 4) = v;
    }
}

// ---------------- final combine: residual + shared + weighted routed --------
__global__ void epilogue_k(const float* __restrict__ x, float* __restrict__ out) {
    int i = blockIdx.x * blockDim.x + threadIdx.x;  // over TOKENS*HD/4
    const int W4 = HD / 4;
    int t = i / W4;
    int h4 = i - t * W4;
    float4 xv = ((const float4*)x)[i];
    float4 sh = ((const float4*)g_o_shared)[i];
    float w0 = g_topw[2 * t], w1 = g_topw[2 * t + 1];
    float4 r0 = *((const float4*)g_o_routed + (size_t)(2 * t) * W4 + h4);
    float4 r1 = *((const float4*)g_o_routed + (size_t)(2 * t + 1) * W4 + h4);
    float4 o;
    o.x = xv.x + sh.x + w0 * r0.x + w1 * r1.x;
    o.y = xv.y + sh.y + w0 * r0.y + w1 * r1.y;
    o.z = xv.z + sh.z + w0 * r0.z + w1 * r1.z;
    o.w = xv.w + sh.w + w0 * r0.w + w1 * r1.w;
    ((float4*)out)[i] = o;
}

// ---------------- launch ----------------------------------------------------
extern "C" void kernel_launch(void* const* d_in, const int* in_sizes, int n_in,
                              void* d_out, int out_size) {
    const float* x  = (const float*)d_in[0];  // [T, H]
    const float* rw = (const float*)d_in[1];  // [E, H]
    const float* sg = (const float*)d_in[2];  // [H, I]
    const float* su = (const float*)d_in[3];  // [H, I]
    const float* sd = (const float*)d_in[4];  // [I, H]
    const float* eg = (const float*)d_in[5];  // [E, H, I]
    const float* eu = (const float*)d_in[6];  // [E, H, I]
    const float* ed = (const float*)d_in[7];  // [E, I, H]
    float* out = (float*)d_out;

    float *h_shared, *o_shared, *h_routed, *o_routed;
    cudaGetSymbolAddress((void**)&h_shared, g_h_shared);
    cudaGetSymbolAddress((void**)&o_shared, g_o_shared);
    cudaGetSymbolAddress((void**)&h_routed, g_h_routed);
    cudaGetSymbolAddress((void**)&o_routed, g_o_routed);

    zero_counts_k<<<1, 32>>>();
    router_k<<<TOKENS / 8, 256>>>(x, rw);

    // shared expert: fused gate/up SwiGLU -> h_shared, then down -> o_shared
    gemm_k<true, 0><<<dim3(ID / BN, TOKENS / BM), 256>>>(x, sg, su, h_shared, ID, HD, 0);
    gemm_k<false, 0><<<dim3(HD / BN, TOKENS / BM), 256>>>(h_shared, sd, nullptr, o_shared, HD, ID, 0);

    // routed experts (grouped, gathered): gate/up -> h_routed, down -> o_routed
    gemm_k<true, 1><<<dim3(ID / BN, NE * (TOKENS / BM)), 256>>>(
        x, eg, eu, h_routed, ID, HD, (long)HD * ID);
    gemm_k<false, 2><<<dim3(HD / BN, NE * (TOKENS / BM)), 256>>>(
        h_routed, ed, nullptr, o_routed, HD, ID, (long)ID * HD);

    epilogue_k<<<(TOKENS * HD / 4) / 256, 256>>>(x, out);
}

// round 3
// speedup vs baseline: 2.7366x; 2.7366x over previous
#include <cuda_runtime.h>
#include <cuda_bf16.h>
#include <math.h>
#include <stdint.h>

#define TOKENS 4096
#define NE 8
#define NPAIR 8192
#define KD 1024
#define NMAT 27            // 3 shared + 8*3 expert matrices (transposed)

typedef __nv_bfloat16 bf16;

// ---------------- scratch (device globals; no allocations allowed) ----------
__device__ __align__(16) bf16 g_xh[(size_t)TOKENS * KD];
__device__ __align__(16) bf16 g_xl[(size_t)TOKENS * KD];
__device__ __align__(16) bf16 g_wTh[(size_t)NMAT * KD * KD];
__device__ __align__(16) bf16 g_wTl[(size_t)NMAT * KD * KD];
__device__ __align__(16) bf16 g_hsh[(size_t)TOKENS * KD];
__device__ __align__(16) bf16 g_hsl[(size_t)TOKENS * KD];
__device__ __align__(16) bf16 g_hrh[(size_t)NPAIR * KD];
__device__ __align__(16) bf16 g_hrl[(size_t)NPAIR * KD];
__device__ __align__(16) float g_tmp1[(size_t)NPAIR * KD];
__device__ __align__(16) float g_tmp2[(size_t)NPAIR * KD];
__device__ __align__(16) float g_o_shared[(size_t)TOKENS * KD];
__device__ __align__(16) float g_o_routed[(size_t)NPAIR * KD];
__device__ float g_topw[NPAIR];
__device__ int   g_counts[NE];
__device__ int   g_lists[NE * TOKENS];

// ---------------- PTX helpers (portable ISA only: sm_80+) --------------------
__device__ __forceinline__ uint32_t smem_to_u32(const void* p) {
    uint32_t a;
    asm("{ .reg .u64 t; cvta.to.shared.u64 t, %1; cvt.u32.u64 %0, t; }" : "=r"(a) : "l"(p));
    return a;
}
__device__ __forceinline__ void cp16(uint32_t dst, const void* src) {
    asm volatile("cp.async.cg.shared.global [%0], [%1], 16;" :: "r"(dst), "l"(src));
}
#define CP_COMMIT() asm volatile("cp.async.commit_group;" ::: "memory")
#define CP_WAIT1()  asm volatile("cp.async.wait_group 1;" ::: "memory")
#define CP_WAIT0()  asm volatile("cp.async.wait_group 0;" ::: "memory")

__device__ __forceinline__ void ldsm4(uint32_t* r, uint32_t addr) {
    asm volatile("ldmatrix.sync.aligned.m8n8.x4.shared.b16 {%0,%1,%2,%3}, [%4];"
                 : "=r"(r[0]), "=r"(r[1]), "=r"(r[2]), "=r"(r[3]) : "r"(addr));
}
__device__ __forceinline__ void mma16816(float* c, const uint32_t* a,
                                         uint32_t b0, uint32_t b1) {
    asm volatile("mma.sync.aligned.m16n8k16.row.col.f32.bf16.bf16.f32 "
                 "{%0,%1,%2,%3}, {%4,%5,%6,%7}, {%8,%9}, {%0,%1,%2,%3};"
                 : "+f"(c[0]), "+f"(c[1]), "+f"(c[2]), "+f"(c[3])
                 : "r"(a[0]), "r"(a[1]), "r"(a[2]), "r"(a[3]), "r"(b0), "r"(b1));
}

// ---------------- bf16 hi/lo split helpers ----------------------------------
__device__ __forceinline__ void split2(float a, float b, uint32_t& h, uint32_t& l) {
    bf16 ha = __float2bfloat16(a), hb = __float2bfloat16(b);
    float ra = a - __bfloat162float(ha);
    float rb = b - __bfloat162float(hb);
    __nv_bfloat162 hp; hp.x = ha; hp.y = hb;
    __nv_bfloat162 lp; lp.x = __float2bfloat16(ra); lp.y = __float2bfloat16(rb);
    h = *(uint32_t*)&hp;
    l = *(uint32_t*)&lp;
}

// ---------------- setup kernels ----------------------------------------------
__global__ void zero_counts_k() { if (threadIdx.x < NE) g_counts[threadIdx.x] = 0; }

__global__ void convert_x_k(const float* __restrict__ x) {
    size_t i = (size_t)blockIdx.x * 256 + threadIdx.x;
#pragma unroll
    for (int j = 0; j < 2; j++) {
        size_t idx = i + (size_t)j * 524288;
        float4 v = ((const float4*)x)[idx];
        uint32_t h0, l0, h1, l1;
        split2(v.x, v.y, h0, l0);
        split2(v.z, v.w, h1, l1);
        ((uint2*)g_xh)[idx] = make_uint2(h0, h1);
        ((uint2*)g_xl)[idx] = make_uint2(l0, l1);
    }
}

// transpose + split weights: [K][N] fp32 -> out[n][k] bf16 hi/lo
__global__ __launch_bounds__(256) void transpose_w_k(
    const float* __restrict__ sg, const float* __restrict__ su,
    const float* __restrict__ sd, const float* __restrict__ eg,
    const float* __restrict__ eu, const float* __restrict__ ed)
{
    __shared__ float t[64][33];
    int slot = blockIdx.z;
    const float* src;
    if      (slot == 0) src = sg;
    else if (slot == 1) src = su;
    else if (slot == 2) src = sd;
    else if (slot < 11) src = eg + (size_t)(slot - 3) * KD * KD;
    else if (slot < 19) src = eu + (size_t)(slot - 11) * KD * KD;
    else                src = ed + (size_t)(slot - 19) * KD * KD;
    int k0 = blockIdx.x * 64, n0 = blockIdx.y * 32;
    int tx = threadIdx.x & 31, ty = threadIdx.x >> 5;
#pragma unroll
    for (int i = 0; i < 8; i++) {
        int r = ty + i * 8;
        t[r][tx] = src[(size_t)(k0 + r) * KD + n0 + tx];
    }
    __syncthreads();
    bf16* oh = g_wTh + (size_t)slot * KD * KD;
    bf16* ol = g_wTl + (size_t)slot * KD * KD;
#pragma unroll
    for (int i = 0; i < 4; i++) {
        int r = ty + i * 8;
        uint32_t h, l;
        split2(t[2 * tx][r], t[2 * tx + 1][r], h, l);
        ((uint32_t*)(oh + (size_t)(n0 + r) * KD + k0))[tx] = h;
        ((uint32_t*)(ol + (size_t)(n0 + r) * KD + k0))[tx] = l;
    }
}

// ---------------- router ------------------------------------------------------
__global__ void router_k(const float* __restrict__ x, const float* __restrict__ rw) {
    int warp = (blockIdx.x * blockDim.x + threadIdx.x) >> 5;
    int lane = threadIdx.x & 31;
    if (warp >= TOKENS) return;
    const float* xr = x + (size_t)warp * KD;
    float acc[NE];
#pragma unroll
    for (int e = 0; e < NE; e++) acc[e] = 0.f;
    for (int h = lane; h < KD; h += 32) {
        float xv = xr[h];
#pragma unroll
        for (int e = 0; e < NE; e++) acc[e] = fmaf(xv, rw[e * KD + h], acc[e]);
    }
#pragma unroll
    for (int e = 0; e < NE; e++)
#pragma unroll
        for (int o = 16; o > 0; o >>= 1)
            acc[e] += __shfl_down_sync(0xffffffffu, acc[e], o);
    if (lane == 0) {
        float mx = acc[0];
#pragma unroll
        for (int e = 1; e < NE; e++) mx = fmaxf(mx, acc[e]);
        float s[NE]; float sum = 0.f;
#pragma unroll
        for (int e = 0; e < NE; e++) { s[e] = expf(acc[e] - mx); sum += s[e]; }
        float inv = 1.f / sum;
        int i1 = 0; float v1 = s[0];
#pragma unroll
        for (int e = 1; e < NE; e++) if (s[e] > v1) { v1 = s[e]; i1 = e; }
        int i2 = -1; float v2 = -1.f;
#pragma unroll
        for (int e = 0; e < NE; e++) if (e != i1 && s[e] > v2) { v2 = s[e]; i2 = e; }
        int t = warp;
        g_topw[t * 2 + 0] = v1 * inv;
        g_topw[t * 2 + 1] = v2 * inv;
        int s1 = atomicAdd(&g_counts[i1], 1); g_lists[i1 * TOKENS + s1] = t * 2;
        int s2 = atomicAdd(&g_counts[i2], 1); g_lists[i2 * TOKENS + s2] = t * 2 + 1;
    }
}

// ---------------- HMMA GEMM --------------------------------------------------
// C[dst,:] = A[src,:] @ W^T, W stored [n][k] bf16 hi/lo. 3-term split.
// Tile 128m x 128n, K staged by 64, double-buffered cp.async.
// GMODE: 0 plain, 1 gather src=pair>>1, 2 gather src=pair.

#define STAGE_BYTES (64 * 1024)
// stage offsets: Ah 0, Al 16K, Bh 32K, Bl 48K

__device__ __forceinline__ void stage_load(
    uint32_t sbase, const bf16* __restrict__ Ah, const bf16* __restrict__ Al,
    const bf16* __restrict__ Wh, const bf16* __restrict__ Wl,
    const int* s_src, int m0, int n0, int k0, int tid)
{
#pragma unroll
    for (int i = 0; i < 4; i++) {
        int chunk = tid + i * 256;
        int row = chunk >> 3, cc = chunk & 7;
        uint32_t off = row * 128 + ((cc * 16) ^ ((row & 7) << 4));
        int arow = s_src ? s_src[row] : (m0 + row);
        const bf16* pa = Ah + (size_t)arow * KD + k0 + cc * 8;
        const bf16* pl = Al + (size_t)arow * KD + k0 + cc * 8;
        cp16(sbase + off, pa);
        cp16(sbase + 16384 + off, pl);
        const bf16* pb = Wh + (size_t)(n0 + row) * KD + k0 + cc * 8;
        const bf16* pc = Wl + (size_t)(n0 + row) * KD + k0 + cc * 8;
        cp16(sbase + 32768 + off, pb);
        cp16(sbase + 49152 + off, pc);
    }
}

template<int GMODE>
__global__ __launch_bounds__(256, 1)
void hgemm_k(const bf16* __restrict__ Ah, const bf16* __restrict__ Al,
             int slotW, float* __restrict__ C)
{
    extern __shared__ __align__(1024) char dynsm[];
    __shared__ int s_src[GMODE ? 128 : 1];
    __shared__ int s_dst[GMODE ? 128 : 1];

    const int tid = threadIdx.x;
    const int wid = tid >> 5, lane = tid & 31;
    const int n0 = blockIdx.x * 128;
    int mtile = blockIdx.y;
    int slot = slotW;

    if (GMODE) {
        int e = blockIdx.y >> 5;
        mtile = blockIdx.y & 31;
        int count = g_counts[e];
        if (mtile * 128 >= count) return;
        slot = slotW + e;
        for (int r = tid; r < 128; r += 256) {
            int idx = mtile * 128 + r;
            if (idx < count) {
                int p = g_lists[e * TOKENS + idx];
                s_dst[r] = p;
                s_src[r] = (GMODE == 1) ? (p >> 1) : p;
            } else { s_dst[r] = -1; s_src[r] = 0; }
        }
        __syncthreads();
    }
    const int m0 = mtile * 128;
    const bf16* Wh = g_wTh + (size_t)slot * KD * KD;
    const bf16* Wl = g_wTl + (size_t)slot * KD * KD;
    const int* srcp = GMODE ? s_src : (const int*)nullptr;

    const uint32_t smbase = smem_to_u32(dynsm);

    // fragment address precompute
    const int warpM = wid >> 2, warpN = wid & 3;   // 2 x 4 warps
    const int mi = lane >> 3, ri = lane & 7;
    const int aRowBase = warpM * 64 + ((mi & 1) << 3) + ri;
    const int aKoff = (mi >> 1) << 4;
    const uint32_t aSwz = (aRowBase & 7) << 4;
    const int bRowBase = warpN * 32 + ((mi >> 1) << 3) + ri;
    const int bKoff = (mi & 1) << 4;
    const uint32_t bSwz = (bRowBase & 7) << 4;

    float acc[4][4][4];
#pragma unroll
    for (int i = 0; i < 4; i++)
#pragma unroll
        for (int j = 0; j < 4; j++)
#pragma unroll
            for (int q = 0; q < 4; q++) acc[i][j][q] = 0.f;

    stage_load(smbase, Ah, Al, Wh, Wl, srcp, m0, n0, 0, tid);
    CP_COMMIT();

    for (int kt = 0; kt < 16; kt++) {
        const uint32_t buf = smbase + (kt & 1) * STAGE_BYTES;
        if (kt < 15) {
            stage_load(smbase + ((kt + 1) & 1) * STAGE_BYTES,
                       Ah, Al, Wh, Wl, srcp, m0, n0, (kt + 1) * 64, tid);
            CP_COMMIT();
            CP_WAIT1();
        } else {
            CP_WAIT0();
        }
        __syncthreads();

#pragma unroll
        for (int ks = 0; ks < 4; ks++) {
            uint32_t ah[4][4], al[4][4], bh[2][4], bl[2][4];
#pragma unroll
            for (int ms = 0; ms < 4; ms++) {
                uint32_t off = (uint32_t)(aRowBase + ms * 16) * 128
                             + (((uint32_t)(ks * 32 + aKoff)) ^ aSwz);
                ldsm4(ah[ms], buf + off);
                ldsm4(al[ms], buf + 16384 + off);
            }
#pragma unroll
            for (int np = 0; np < 2; np++) {
                uint32_t off = (uint32_t)(bRowBase + np * 16) * 128
                             + (((uint32_t)(ks * 32 + bKoff)) ^ bSwz);
                ldsm4(bh[np], buf + 32768 + off);
                ldsm4(bl[np], buf + 49152 + off);
            }
#pragma unroll
            for (int ms = 0; ms < 4; ms++)
#pragma unroll
                for (int ns = 0; ns < 4; ns++) {
                    int np = ns >> 1, h = (ns & 1) << 1;
                    mma16816(acc[ms][ns], ah[ms], bh[np][h], bh[np][h + 1]);
                    mma16816(acc[ms][ns], ah[ms], bl[np][h], bl[np][h + 1]);
                    mma16816(acc[ms][ns], al[ms], bh[np][h], bh[np][h + 1]);
                }
        }
        __syncthreads();
    }

    // epilogue: C fragment rows
    const int rbase = lane >> 2;
    const int cbase = (lane & 3) * 2;
#pragma unroll
    for (int ms = 0; ms < 4; ms++) {
        int lm = warpM * 64 + ms * 16 + rbase;
#pragma unroll
        for (int half = 0; half < 2; half++) {
            int lmr = lm + half * 8;
            int dst = GMODE ? s_dst[lmr] : (m0 + lmr);
            if (GMODE && dst < 0) continue;
            float* crow = C + (size_t)dst * KD + n0 + warpN * 32 + cbase;
#pragma unroll
            for (int ns = 0; ns < 4; ns++) {
                float2 v;
                v.x = acc[ms][ns][half * 2];
                v.y = acc[ms][ns][half * 2 + 1];
                *(float2*)(crow + ns * 8) = v;
            }
        }
    }
}

// ---------------- SwiGLU + split ---------------------------------------------
__global__ void swiglu_k(const float* __restrict__ g, const float* __restrict__ u,
                         bf16* __restrict__ hh, bf16* __restrict__ hl) {
    size_t i = (size_t)blockIdx.x * 256 + threadIdx.x;   // over rows*KD/4
    float4 gv = ((const float4*)g)[i];
    float4 uv = ((const float4*)u)[i];
    float h0 = uv.x / (1.f + expf(-gv.x));
    float h1 = uv.y / (1.f + expf(-gv.y));
    float h2 = uv.z / (1.f + expf(-gv.z));
    float h3 = uv.w / (1.f + expf(-gv.w));
    uint32_t a, b, c, d;
    split2(h0, h1, a, b);
    split2(h2, h3, c, d);
    ((uint2*)hh)[i] = make_uint2(a, c);
    ((uint2*)hl)[i] = make_uint2(b, d);
}

// ---------------- final combine ----------------------------------------------
__global__ void epilogue_k(const float* __restrict__ x, float* __restrict__ out) {
    int i = blockIdx.x * blockDim.x + threadIdx.x;
    const int W4 = KD / 4;
    int t = i / W4;
    int h4 = i - t * W4;
    float4 xv = ((const float4*)x)[i];
    float4 sh = ((const float4*)g_o_shared)[i];
    float w0 = g_topw[2 * t], w1 = g_topw[2 * t + 1];
    float4 r0 = *((const float4*)g_o_routed + (size_t)(2 * t) * W4 + h4);
    float4 r1 = *((const float4*)g_o_routed + (size_t)(2 * t + 1) * W4 + h4);
    float4 o;
    o.x = xv.x + sh.x + w0 * r0.x + w1 * r1.x;
    o.y = xv.y + sh.y + w0 * r0.y + w1 * r1.y;
    o.z = xv.z + sh.z + w0 * r0.z + w1 * r1.z;
    o.w = xv.w + sh.w + w0 * r0.w + w1 * r1.w;
    ((float4*)out)[i] = o;
}

// ---------------- launch ------------------------------------------------------
extern "C" void kernel_launch(void* const* d_in, const int* in_sizes, int n_in,
                              void* d_out, int out_size) {
    const float* x  = (const float*)d_in[0];
    const float* rw = (const float*)d_in[1];
    const float* sg = (const float*)d_in[2];
    const float* su = (const float*)d_in[3];
    const float* sd = (const float*)d_in[4];
    const float* eg = (const float*)d_in[5];
    const float* eu = (const float*)d_in[6];
    const float* ed = (const float*)d_in[7];
    float* out = (float*)d_out;

    bf16 *xh, *xl, *hsh, *hsl, *hrh, *hrl;
    float *tmp1, *tmp2, *o_shared, *o_routed;
    cudaGetSymbolAddress((void**)&xh, g_xh);
    cudaGetSymbolAddress((void**)&xl, g_xl);
    cudaGetSymbolAddress((void**)&hsh, g_hsh);
    cudaGetSymbolAddress((void**)&hsl, g_hsl);
    cudaGetSymbolAddress((void**)&hrh, g_hrh);
    cudaGetSymbolAddress((void**)&hrl, g_hrl);
    cudaGetSymbolAddress((void**)&tmp1, g_tmp1);
    cudaGetSymbolAddress((void**)&tmp2, g_tmp2);
    cudaGetSymbolAddress((void**)&o_shared, g_o_shared);
    cudaGetSymbolAddress((void**)&o_routed, g_o_routed);

    const int SMSZ = 2 * STAGE_BYTES;
    cudaFuncSetAttribute(hgemm_k<0>, cudaFuncAttributeMaxDynamicSharedMemorySize, SMSZ);
    cudaFuncSetAttribute(hgemm_k<1>, cudaFuncAttributeMaxDynamicSharedMemorySize, SMSZ);
    cudaFuncSetAttribute(hgemm_k<2>, cudaFuncAttributeMaxDynamicSharedMemorySize, SMSZ);

    zero_counts_k<<<1, 32>>>();
    convert_x_k<<<2048, 256>>>(x);
    transpose_w_k<<<dim3(16, 32, NMAT), 256>>>(sg, su, sd, eg, eu, ed);
    router_k<<<TOKENS / 8, 256>>>(x, rw);

    // shared expert
    hgemm_k<0><<<dim3(8, 32), 256, SMSZ>>>(xh, xl, 0, tmp1);   // gate
    hgemm_k<0><<<dim3(8, 32), 256, SMSZ>>>(xh, xl, 1, tmp2);   // up
    swiglu_k<<<TOKENS * KD / 4 / 256, 256>>>(tmp1, tmp2, hsh, hsl);
    hgemm_k<0><<<dim3(8, 32), 256, SMSZ>>>(hsh, hsl, 2, o_shared);

    // routed experts (grouped + gathered)
    hgemm_k<1><<<dim3(8, NE * 32), 256, SMSZ>>>(xh, xl, 3,  tmp1);   // gate
    hgemm_k<1><<<dim3(8, NE * 32), 256, SMSZ>>>(xh, xl, 11, tmp2);   // up
    swiglu_k<<<NPAIR * KD / 4 / 256, 256>>>(tmp1, tmp2, hrh, hrl);
    hgemm_k<2><<<dim3(8, NE * 32), 256, SMSZ>>>(hrh, hrl, 19, o_routed);

    epilogue_k<<<(TOKENS * KD / 4) / 256, 256>>>(x, out);
}

// round 4
// speedup vs baseline: 5.5300x; 2.0207x over previous
#include <cuda_runtime.h>
#include <cuda_fp16.h>
#include <math.h>
#include <stdint.h>

#define TOKENS 4096
#define NE 8
#define NPAIR 8192
#define KD 1024
#define NMAT 27            // 0 sg, 1 su, 2 sd, 3..10 eg, 11..18 eu, 19..26 ed

typedef __half half_t;

// ---------------- scratch (device globals; no allocations allowed) ----------
__device__ __align__(16) half_t g_xh[(size_t)TOKENS * KD];          // x fp16
__device__ __align__(16) half_t g_wT[(size_t)NMAT * KD * KD];       // W^T fp16
__device__ __align__(16) half_t g_hs[(size_t)TOKENS * KD];          // shared hidden
__device__ __align__(16) half_t g_hr[(size_t)NPAIR * KD];           // routed hidden
__device__ __align__(16) float g_o_shared[(size_t)TOKENS * KD];
__device__ __align__(16) float g_o_routed[(size_t)NPAIR * KD];
__device__ float g_topw[NPAIR];
__device__ int   g_counts[NE];
__device__ int   g_lists[NE * TOKENS];

// ---------------- PTX helpers (portable ISA, sm_80+) -------------------------
__device__ __forceinline__ uint32_t smem_to_u32(const void* p) {
    uint32_t a;
    asm("{ .reg .u64 t; cvta.to.shared.u64 t, %1; cvt.u32.u64 %0, t; }" : "=r"(a) : "l"(p));
    return a;
}
__device__ __forceinline__ void cp16(uint32_t dst, const void* src) {
    asm volatile("cp.async.cg.shared.global [%0], [%1], 16;" :: "r"(dst), "l"(src));
}
#define CP_COMMIT() asm volatile("cp.async.commit_group;" ::: "memory")
#define CP_WAIT1()  asm volatile("cp.async.wait_group 1;" ::: "memory")
#define CP_WAIT0()  asm volatile("cp.async.wait_group 0;" ::: "memory")

__device__ __forceinline__ void ldsm4(uint32_t* r, uint32_t addr) {
    asm volatile("ldmatrix.sync.aligned.m8n8.x4.shared.b16 {%0,%1,%2,%3}, [%4];"
                 : "=r"(r[0]), "=r"(r[1]), "=r"(r[2]), "=r"(r[3]) : "r"(addr));
}
__device__ __forceinline__ void mma16816(float* c, const uint32_t* a,
                                         uint32_t b0, uint32_t b1) {
    asm volatile("mma.sync.aligned.m16n8k16.row.col.f32.f16.f16.f32 "
                 "{%0,%1,%2,%3}, {%4,%5,%6,%7}, {%8,%9}, {%0,%1,%2,%3};"
                 : "+f"(c[0]), "+f"(c[1]), "+f"(c[2]), "+f"(c[3])
                 : "r"(a[0]), "r"(a[1]), "r"(a[2]), "r"(a[3]), "r"(b0), "r"(b1));
}
__device__ __forceinline__ uint32_t pack_h2(float a, float b) {
    __half2 h = __floats2half2_rn(a, b);
    return *(uint32_t*)&h;
}

// ---------------- setup -------------------------------------------------------
__global__ void zero_counts_k() { if (threadIdx.x < NE) g_counts[threadIdx.x] = 0; }

// fused: x fp32 -> fp16 conversion AND router softmax/top2/compaction
__global__ __launch_bounds__(256)
void convert_router_k(const float* __restrict__ x, const float* __restrict__ rw) {
    int t = (blockIdx.x * blockDim.x + threadIdx.x) >> 5;
    int lane = threadIdx.x & 31;
    const float* xr = x + (size_t)t * KD;
    float acc[NE];
#pragma unroll
    for (int e = 0; e < NE; e++) acc[e] = 0.f;
#pragma unroll
    for (int i = 0; i < 8; i++) {
        int h = lane * 4 + i * 128;
        float4 v = *(const float4*)(xr + h);
        uint2 p;
        p.x = pack_h2(v.x, v.y);
        p.y = pack_h2(v.z, v.w);
        *(uint2*)(g_xh + (size_t)t * KD + h) = p;
#pragma unroll
        for (int e = 0; e < NE; e++) {
            float4 w = *(const float4*)(rw + e * KD + h);
            acc[e] = fmaf(v.x, w.x, acc[e]);
            acc[e] = fmaf(v.y, w.y, acc[e]);
            acc[e] = fmaf(v.z, w.z, acc[e]);
            acc[e] = fmaf(v.w, w.w, acc[e]);
        }
    }
#pragma unroll
    for (int e = 0; e < NE; e++)
#pragma unroll
        for (int o = 16; o > 0; o >>= 1)
            acc[e] += __shfl_down_sync(0xffffffffu, acc[e], o);
    if (lane == 0) {
        float mx = acc[0];
#pragma unroll
        for (int e = 1; e < NE; e++) mx = fmaxf(mx, acc[e]);
        float s[NE]; float sum = 0.f;
#pragma unroll
        for (int e = 0; e < NE; e++) { s[e] = expf(acc[e] - mx); sum += s[e]; }
        float inv = 1.f / sum;
        int i1 = 0; float v1 = s[0];
#pragma unroll
        for (int e = 1; e < NE; e++) if (s[e] > v1) { v1 = s[e]; i1 = e; }
        int i2 = -1; float v2 = -1.f;
#pragma unroll
        for (int e = 0; e < NE; e++) if (e != i1 && s[e] > v2) { v2 = s[e]; i2 = e; }
        g_topw[t * 2 + 0] = v1 * inv;
        g_topw[t * 2 + 1] = v2 * inv;
        int s1 = atomicAdd(&g_counts[i1], 1); g_lists[i1 * TOKENS + s1] = t * 2;
        int s2 = atomicAdd(&g_counts[i2], 1); g_lists[i2 * TOKENS + s2] = t * 2 + 1;
    }
}

// transpose weights: [K][N] fp32 -> [n][k] fp16
__global__ __launch_bounds__(256) void transpose_w_k(
    const float* __restrict__ sg, const float* __restrict__ su,
    const float* __restrict__ sd, const float* __restrict__ eg,
    const float* __restrict__ eu, const float* __restrict__ ed)
{
    __shared__ float t[64][33];
    int slot = blockIdx.z;
    const float* src;
    if      (slot == 0) src = sg;
    else if (slot == 1) src = su;
    else if (slot == 2) src = sd;
    else if (slot < 11) src = eg + (size_t)(slot - 3) * KD * KD;
    else if (slot < 19) src = eu + (size_t)(slot - 11) * KD * KD;
    else                src = ed + (size_t)(slot - 19) * KD * KD;
    int k0 = blockIdx.x * 64, n0 = blockIdx.y * 32;
    int tx = threadIdx.x & 31, ty = threadIdx.x >> 5;
#pragma unroll
    for (int i = 0; i < 8; i++) {
        int r = ty + i * 8;
        t[r][tx] = src[(size_t)(k0 + r) * KD + n0 + tx];
    }
    __syncthreads();
    half_t* oh = g_wT + (size_t)slot * KD * KD;
#pragma unroll
    for (int i = 0; i < 4; i++) {
        int r = ty + i * 8;
        ((uint32_t*)(oh + (size_t)(n0 + r) * KD + k0))[tx] =
            pack_h2(t[2 * tx][r], t[2 * tx + 1][r]);
    }
}

// ---------------- single-matrix HMMA GEMM (down-proj) ------------------------
// C[dst,:] = A[src,:] @ W^T (fp16, fp32 accum). Tile 128m x 128n, K staged 64.
// GMODE: 0 plain, 2 gather src=pair (hidden rows).
#define STAGE_S 32768
// stage layout: A 0..16K, B 16K..32K

__device__ __forceinline__ void stage_load_s(
    uint32_t sbase, const half_t* __restrict__ A, const half_t* __restrict__ W,
    const int* s_src, int m0, int n0, int k0, int tid)
{
#pragma unroll
    for (int i = 0; i < 4; i++) {
        int chunk = tid + i * 256;
        int row = chunk >> 3, cc = chunk & 7;
        uint32_t off = row * 128 + ((cc * 16) ^ ((row & 7) << 4));
        int arow = s_src ? s_src[row] : (m0 + row);
        cp16(sbase + off, A + (size_t)arow * KD + k0 + cc * 8);
        cp16(sbase + 16384 + off, W + (size_t)(n0 + row) * KD + k0 + cc * 8);
    }
}

template<int GMODE>
__global__ __launch_bounds__(256, 1)
void hgemm_k(const half_t* __restrict__ A, int slotW, float* __restrict__ C)
{
    extern __shared__ __align__(1024) char dynsm[];
    __shared__ int s_src[GMODE ? 128 : 1];
    __shared__ int s_dst[GMODE ? 128 : 1];

    const int tid = threadIdx.x;
    const int wid = tid >> 5, lane = tid & 31;
    const int n0 = blockIdx.x * 128;
    int mtile = blockIdx.y;
    int slot = slotW;
    float scale = 1.f;

    if (GMODE) {
        int e = blockIdx.y >> 5;
        mtile = blockIdx.y & 31;
        int count = g_counts[e];
        if (mtile * 128 >= count) return;
        slot = slotW + e;
        for (int r = tid; r < 128; r += 256) {
            int idx = mtile * 128 + r;
            if (idx < count) {
                int p = g_lists[e * TOKENS + idx];
                s_dst[r] = p;
                s_src[r] = p;
            } else { s_dst[r] = -1; s_src[r] = 0; }
        }
        __syncthreads();
    }
    const int m0 = mtile * 128;
    const half_t* W = g_wT + (size_t)slot * KD * KD;
    const int* srcp = GMODE ? s_src : (const int*)nullptr;
    const uint32_t smbase = smem_to_u32(dynsm);

    const int warpM = wid >> 2, warpN = wid & 3;
    const int mi = lane >> 3, ri = lane & 7;
    const int aRowBase = warpM * 64 + ((mi & 1) << 3) + ri;
    const int aKoff = (mi >> 1) << 4;
    const uint32_t aSwz = (aRowBase & 7) << 4;
    const int bRowBase = warpN * 32 + ((mi >> 1) << 3) + ri;
    const int bKoff = (mi & 1) << 4;
    const uint32_t bSwz = (bRowBase & 7) << 4;

    float acc[4][4][4];
#pragma unroll
    for (int i = 0; i < 4; i++)
#pragma unroll
        for (int j = 0; j < 4; j++)
#pragma unroll
            for (int q = 0; q < 4; q++) acc[i][j][q] = 0.f;

    stage_load_s(smbase, A, W, srcp, m0, n0, 0, tid);
    CP_COMMIT();

    for (int kt = 0; kt < 16; kt++) {
        const uint32_t buf = smbase + (kt & 1) * STAGE_S;
        if (kt < 15) {
            stage_load_s(smbase + ((kt + 1) & 1) * STAGE_S, A, W, srcp, m0, n0,
                         (kt + 1) * 64, tid);
            CP_COMMIT();
            CP_WAIT1();
        } else {
            CP_WAIT0();
        }
        __syncthreads();
#pragma unroll
        for (int ks = 0; ks < 4; ks++) {
            uint32_t a[4][4], b[2][4];
#pragma unroll
            for (int ms = 0; ms < 4; ms++) {
                uint32_t off = (uint32_t)(aRowBase + ms * 16) * 128
                             + (((uint32_t)(ks * 32 + aKoff)) ^ aSwz);
                ldsm4(a[ms], buf + off);
            }
#pragma unroll
            for (int np = 0; np < 2; np++) {
                uint32_t off = (uint32_t)(bRowBase + np * 16) * 128
                             + (((uint32_t)(ks * 32 + bKoff)) ^ bSwz);
                ldsm4(b[np], buf + 16384 + off);
            }
#pragma unroll
            for (int ms = 0; ms < 4; ms++)
#pragma unroll
                for (int ns = 0; ns < 4; ns++) {
                    int np = ns >> 1, h = (ns & 1) << 1;
                    mma16816(acc[ms][ns], a[ms], b[np][h], b[np][h + 1]);
                }
        }
        __syncthreads();
    }

    const int rbase = lane >> 2;
    const int cbase = (lane & 3) * 2;
#pragma unroll
    for (int ms = 0; ms < 4; ms++) {
        int lm = warpM * 64 + ms * 16 + rbase;
#pragma unroll
        for (int half = 0; half < 2; half++) {
            int lmr = lm + half * 8;
            int dst = GMODE ? s_dst[lmr] : (m0 + lmr);
            if (GMODE && dst < 0) continue;
            float* crow = C + (size_t)dst * KD + n0 + warpN * 32 + cbase;
#pragma unroll
            for (int ns = 0; ns < 4; ns++) {
                float2 v;
                v.x = acc[ms][ns][half * 2];
                v.y = acc[ms][ns][half * 2 + 1];
                *(float2*)(crow + ns * 8) = v;
            }
        }
    }
}

// ---------------- dual-matrix (gate+up) GEMM with fused SwiGLU ---------------
// Computes g = A@Wg^T, u = A@Wu^T for a 128m x 64n tile of each,
// writes h = sigmoid(g)*u as fp16 to H. K staged by 64.
// GMODE: 0 plain (shared), 1 gather src = pair>>1 (routed, A = x rows).
#define STAGE_D 32768
// stage layout: A 0..16K, Bg 16K..24K, Bu 24K..32K

__device__ __forceinline__ void stage_load_d(
    uint32_t sbase, const half_t* __restrict__ A, const half_t* __restrict__ Wg,
    const half_t* __restrict__ Wu, const int* s_src, int m0, int n0, int k0, int tid)
{
#pragma unroll
    for (int i = 0; i < 4; i++) {
        int chunk = tid + i * 256;
        int row = chunk >> 3, cc = chunk & 7;
        uint32_t off = row * 128 + ((cc * 16) ^ ((row & 7) << 4));
        int arow = s_src ? s_src[row] : (m0 + row);
        cp16(sbase + off, A + (size_t)arow * KD + k0 + cc * 8);
    }
#pragma unroll
    for (int i = 0; i < 2; i++) {
        int chunk = tid + i * 256;
        int row = chunk >> 3, cc = chunk & 7;   // row 0..63
        uint32_t off = row * 128 + ((cc * 16) ^ ((row & 7) << 4));
        cp16(sbase + 16384 + off, Wg + (size_t)(n0 + row) * KD + k0 + cc * 8);
        cp16(sbase + 24576 + off, Wu + (size_t)(n0 + row) * KD + k0 + cc * 8);
    }
}

template<int GMODE>
__global__ __launch_bounds__(256, 1)
void dualgemm_k(const half_t* __restrict__ A, int slotG, int slotU,
                half_t* __restrict__ H)
{
    extern __shared__ __align__(1024) char dynsm[];
    __shared__ int s_src[GMODE ? 128 : 1];
    __shared__ int s_dst[GMODE ? 128 : 1];

    const int tid = threadIdx.x;
    const int wid = tid >> 5, lane = tid & 31;
    const int n0 = blockIdx.x * 64;
    int mtile = blockIdx.y;
    int eoff = 0;

    if (GMODE) {
        int e = blockIdx.y >> 5;
        mtile = blockIdx.y & 31;
        int count = g_counts[e];
        if (mtile * 128 >= count) return;
        eoff = e;
        for (int r = tid; r < 128; r += 256) {
            int idx = mtile * 128 + r;
            if (idx < count) {
                int p = g_lists[e * TOKENS + idx];
                s_dst[r] = p;
                s_src[r] = p >> 1;
            } else { s_dst[r] = -1; s_src[r] = 0; }
        }
        __syncthreads();
    }
    const int m0 = mtile * 128;
    const half_t* Wg = g_wT + (size_t)(slotG + eoff) * KD * KD;
    const half_t* Wu = g_wT + (size_t)(slotU + eoff) * KD * KD;
    const int* srcp = GMODE ? s_src : (const int*)nullptr;
    const uint32_t smbase = smem_to_u32(dynsm);

    const int warpM = wid >> 2, warpN = wid & 3;   // 2m x 4n, warp = 64m x 16n per matrix
    const int mi = lane >> 3, ri = lane & 7;
    const int aRowBase = warpM * 64 + ((mi & 1) << 3) + ri;
    const int aKoff = (mi >> 1) << 4;
    const uint32_t aSwz = (aRowBase & 7) << 4;
    const int bRowBase = warpN * 16 + ((mi >> 1) << 3) + ri;
    const int bKoff = (mi & 1) << 4;
    const uint32_t bSwz = (bRowBase & 7) << 4;

    float accg[4][2][4], accu[4][2][4];
#pragma unroll
    for (int i = 0; i < 4; i++)
#pragma unroll
        for (int j = 0; j < 2; j++)
#pragma unroll
            for (int q = 0; q < 4; q++) { accg[i][j][q] = 0.f; accu[i][j][q] = 0.f; }

    stage_load_d(smbase, A, Wg, Wu, srcp, m0, n0, 0, tid);
    CP_COMMIT();

    for (int kt = 0; kt < 16; kt++) {
        const uint32_t buf = smbase + (kt & 1) * STAGE_D;
        if (kt < 15) {
            stage_load_d(smbase + ((kt + 1) & 1) * STAGE_D, A, Wg, Wu, srcp,
                         m0, n0, (kt + 1) * 64, tid);
            CP_COMMIT();
            CP_WAIT1();
        } else {
            CP_WAIT0();
        }
        __syncthreads();
#pragma unroll
        for (int ks = 0; ks < 4; ks++) {
            uint32_t a[4][4], bg[4], bu[4];
#pragma unroll
            for (int ms = 0; ms < 4; ms++) {
                uint32_t off = (uint32_t)(aRowBase + ms * 16) * 128
                             + (((uint32_t)(ks * 32 + aKoff)) ^ aSwz);
                ldsm4(a[ms], buf + off);
            }
            {
                uint32_t off = (uint32_t)bRowBase * 128
                             + (((uint32_t)(ks * 32 + bKoff)) ^ bSwz);
                ldsm4(bg, buf + 16384 + off);
                ldsm4(bu, buf + 24576 + off);
            }
#pragma unroll
            for (int ms = 0; ms < 4; ms++)
#pragma unroll
                for (int ns = 0; ns < 2; ns++) {
                    int h = ns << 1;
                    mma16816(accg[ms][ns], a[ms], bg[h], bg[h + 1]);
                    mma16816(accu[ms][ns], a[ms], bu[h], bu[h + 1]);
                }
        }
        __syncthreads();
    }

    const int rbase = lane >> 2;
    const int cbase = (lane & 3) * 2;
#pragma unroll
    for (int ms = 0; ms < 4; ms++) {
        int lm = warpM * 64 + ms * 16 + rbase;
#pragma unroll
        for (int half = 0; half < 2; half++) {
            int lmr = lm + half * 8;
            int dst = GMODE ? s_dst[lmr] : (m0 + lmr);
            if (GMODE && dst < 0) continue;
            half_t* crow = H + (size_t)dst * KD + n0 + warpN * 16 + cbase;
#pragma unroll
            for (int ns = 0; ns < 2; ns++) {
                float g0 = accg[ms][ns][half * 2], g1 = accg[ms][ns][half * 2 + 1];
                float u0 = accu[ms][ns][half * 2], u1 = accu[ms][ns][half * 2 + 1];
                float h0 = u0 / (1.f + expf(-g0));
                float h1 = u1 / (1.f + expf(-g1));
                *(uint32_t*)(crow + ns * 8) = pack_h2(h0, h1);
            }
        }
    }
}

// ---------------- final combine ----------------------------------------------
__global__ void epilogue_k(const float* __restrict__ x, float* __restrict__ out) {
    int i = blockIdx.x * blockDim.x + threadIdx.x;
    const int W4 = KD / 4;
    int t = i / W4;
    int h4 = i - t * W4;
    float4 xv = ((const float4*)x)[i];
    float4 sh = ((const float4*)g_o_shared)[i];
    float w0 = g_topw[2 * t], w1 = g_topw[2 * t + 1];
    float4 r0 = *((const float4*)g_o_routed + (size_t)(2 * t) * W4 + h4);
    float4 r1 = *((const float4*)g_o_routed + (size_t)(2 * t + 1) * W4 + h4);
    float4 o;
    o.x = xv.x + sh.x + w0 * r0.x + w1 * r1.x;
    o.y = xv.y + sh.y + w0 * r0.y + w1 * r1.y;
    o.z = xv.z + sh.z + w0 * r0.z + w1 * r1.z;
    o.w = xv.w + sh.w + w0 * r0.w + w1 * r1.w;
    ((float4*)out)[i] = o;
}

// ---------------- launch ------------------------------------------------------
extern "C" void kernel_launch(void* const* d_in, const int* in_sizes, int n_in,
                              void* d_out, int out_size) {
    const float* x  = (const float*)d_in[0];
    const float* rw = (const float*)d_in[1];
    const float* sg = (const float*)d_in[2];
    const float* su = (const float*)d_in[3];
    const float* sd = (const float*)d_in[4];
    const float* eg = (const float*)d_in[5];
    const float* eu = (const float*)d_in[6];
    const float* ed = (const float*)d_in[7];
    float* out = (float*)d_out;

    half_t *xh, *hs, *hr;
    float *o_shared, *o_routed;
    cudaGetSymbolAddress((void**)&xh, g_xh);
    cudaGetSymbolAddress((void**)&hs, g_hs);
    cudaGetSymbolAddress((void**)&hr, g_hr);
    cudaGetSymbolAddress((void**)&o_shared, g_o_shared);
    cudaGetSymbolAddress((void**)&o_routed, g_o_routed);

    const int SM2 = 2 * STAGE_S;
    cudaFuncSetAttribute(hgemm_k<0>,   cudaFuncAttributeMaxDynamicSharedMemorySize, SM2);
    cudaFuncSetAttribute(hgemm_k<2>,   cudaFuncAttributeMaxDynamicSharedMemorySize, SM2);
    cudaFuncSetAttribute(dualgemm_k<0>, cudaFuncAttributeMaxDynamicSharedMemorySize, SM2);
    cudaFuncSetAttribute(dualgemm_k<1>, cudaFuncAttributeMaxDynamicSharedMemorySize, SM2);

    zero_counts_k<<<1, 32>>>();
    convert_router_k<<<TOKENS / 8, 256>>>(x, rw);
    transpose_w_k<<<dim3(16, 32, NMAT), 256>>>(sg, su, sd, eg, eu, ed);

    // shared expert: fused gate+up+swiglu -> hs (fp16), then down -> o_shared
    dualgemm_k<0><<<dim3(16, 32), 256, SM2>>>(xh, 0, 1, hs);
    hgemm_k<0><<<dim3(8, 32), 256, SM2>>>(hs, 2, o_shared);

    // routed experts: fused gate+up+swiglu (gathered) -> hr, then down -> o_routed
    dualgemm_k<1><<<dim3(16, NE * 32), 256, SM2>>>(xh, 3, 11, hr);
    hgemm_k<2><<<dim3(8, NE * 32), 256, SM2>>>(hr, 19, o_routed);

    epilogue_k<<<(TOKENS * KD / 4) / 256, 256>>>(x, out);
}